// round 2
// baseline (speedup 1.0000x reference)
#include <cuda_runtime.h>
#include <cuda_bf16.h>
#include <cstdint>

// Problem constants (fixed by metadata): B=32, N=300, C=3, H=W=1024
#define BB 32
#define NN 300
#define HH 1024
#define WW 1024
#define NBOX (BB * NN)          // 9600
#define PLANE (1u << 20)        // 1024*1024

// Scratch: column-prefix of (class2 - class1), per batch. 32 * 1M floats = 128 MiB.
__device__ float g_cc[(size_t)BB * PLANE];
// Per-batch bitmask of rows of g_cc that box queries will read (1024 bits = 32 words).
__device__ unsigned g_rowmask[BB * 32];

__device__ __forceinline__ int clampi(int v, int lo, int hi) {
    return v < lo ? lo : (v > hi ? hi : v);
}

// Compute box pixel coords exactly like the reference:
// trunc-toward-zero then clamp to [0, dim-1].
__device__ __forceinline__ void box_coords(const float* __restrict__ boxes, int i,
                                           int& x1, int& x2, int& y1, int& y2) {
    float cx = boxes[i * 4 + 0];
    float cy = boxes[i * 4 + 1];
    float w  = boxes[i * 4 + 2];
    float h  = boxes[i * 4 + 3];
    x1 = clampi((int)((cx - w * 0.5f) * (float)WW), 0, WW - 1);
    x2 = clampi((int)((cx + w * 0.5f) * (float)WW), 0, WW - 1);
    y1 = clampi((int)((cy - h * 0.5f) * (float)HH), 0, HH - 1);
    y2 = clampi((int)((cy + h * 0.5f) * (float)HH), 0, HH - 1);
}

// Kernel 1: single block. Zero output + row masks, then mark needed rows.
__global__ void k_prep(const float* __restrict__ boxes,
                       const float* __restrict__ conf,
                       float* __restrict__ out) {
    int tid = threadIdx.x;
    for (int i = tid; i < BB * 32; i += blockDim.x) g_rowmask[i] = 0u;
    if (tid == 0) out[0] = 0.0f;
    __syncthreads();
    for (int i = tid; i < NBOX; i += blockDim.x) {
        int x1, x2, y1, y2;
        box_coords(boxes, i, x1, x2, y1, y2);
        bool valid = (conf[i] >= 0.3f) && (x2 > x1) && (y2 > y1);
        if (valid) {
            int b = i / NN;
            int rt = y2 - 1;  // y2 >= 1 when valid
            atomicOr(&g_rowmask[b * 32 + (rt >> 5)], 1u << (rt & 31));
            if (y1 > 0) {
                int rb = y1 - 1;
                atomicOr(&g_rowmask[b * 32 + (rb >> 5)], 1u << (rb & 31));
            }
        }
    }
}

// Kernel 2: column-prefix scan of diff = seg[b,2] - seg[b,1].
// grid = (WW/128, BB), block = 128. Each thread owns one column; writes only
// rows that kernel 3 will read (per-batch bitmask).
// The inner loop loads a batch of 8 row-diffs first (independent of the
// loop-carried prefix), then folds them in — keeps >=16 LDGs in flight per
// thread instead of serializing loads behind the FADD chain.
__global__ void k_scan(const float* __restrict__ seg) {
    int b = blockIdx.y;
    int col = blockIdx.x * 128 + threadIdx.x;

    __shared__ unsigned smask[32];
    if (threadIdx.x < 32) smask[threadIdx.x] = g_rowmask[b * 32 + threadIdx.x];
    __syncthreads();

    const float* __restrict__ p1 = seg + ((size_t)(b * 3 + 1)) * PLANE + col;
    const float* __restrict__ p2 = seg + ((size_t)(b * 3 + 2)) * PLANE + col;
    float* __restrict__ pc = g_cc + ((size_t)b) * PLANE + col;

    float run = 0.0f;
    for (int w = 0; w < 32; ++w) {
        unsigned m = smask[w];
#pragma unroll
        for (int g = 0; g < 4; ++g) {
            // batch-load 8 rows worth of diffs (16 independent LDGs)
            float d[8];
#pragma unroll
            for (int i = 0; i < 8; ++i)
                d[i] = p2[(size_t)i * WW] - p1[(size_t)i * WW];
            // fold into prefix; masked stores only
#pragma unroll
            for (int i = 0; i < 8; ++i) {
                run += d[i];
                if ((m >> (g * 8 + i)) & 1u) pc[(size_t)i * WW] = run;
            }
            p1 += 8 * WW;
            p2 += 8 * WW;
            pc += 8 * WW;
        }
    }
}

// Kernel 3: one block per box. Reduce Cc row segments, apply relu/conf, atomicAdd.
__global__ void k_box(const float* __restrict__ boxes,
                      const float* __restrict__ conf,
                      float* __restrict__ out) {
    int i = blockIdx.x;
    int x1, x2, y1, y2;
    box_coords(boxes, i, x1, x2, y1, y2);
    float cf = conf[i];
    bool valid = (cf >= 0.3f) && (x2 > x1) && (y2 > y1);
    if (!valid) return;

    int b = i / NN;
    const float* __restrict__ top = g_cc + ((size_t)b) * PLANE + (size_t)(y2 - 1) * WW;
    float s = 0.0f;
    if (y1 > 0) {
        const float* __restrict__ bot = g_cc + ((size_t)b) * PLANE + (size_t)(y1 - 1) * WW;
        for (int x = x1 + (int)threadIdx.x; x < x2; x += (int)blockDim.x)
            s += top[x] - bot[x];
    } else {
        for (int x = x1 + (int)threadIdx.x; x < x2; x += (int)blockDim.x)
            s += top[x];
    }

    // block reduction (128 threads = 4 warps)
    __shared__ float red[4];
#pragma unroll
    for (int off = 16; off > 0; off >>= 1)
        s += __shfl_down_sync(0xFFFFFFFFu, s, off);
    if ((threadIdx.x & 31) == 0) red[threadIdx.x >> 5] = s;
    __syncthreads();
    if (threadIdx.x == 0) {
        float tot = red[0] + red[1] + red[2] + red[3];
        float area = (float)((y2 - y1) * (x2 - x1));
        float pb = fmaxf(tot / area, 0.0f) * cf;
        atomicAdd(out, pb * (1.0f / (float)NBOX));
    }
}

extern "C" void kernel_launch(void* const* d_in, const int* in_sizes, int n_in,
                              void* d_out, int out_size) {
    const float* boxes = (const float*)d_in[0];   // (32,300,4)
    const float* conf  = (const float*)d_in[1];   // (32,300)
    const float* seg   = (const float*)d_in[2];   // (32,3,1024,1024)
    float* out = (float*)d_out;

    k_prep<<<1, 256>>>(boxes, conf, out);
    dim3 gscan(WW / 128, BB);
    k_scan<<<gscan, 128>>>(seg);
    k_box<<<NBOX, 128>>>(boxes, conf, out);
}

// round 3
// speedup vs baseline: 1.9921x; 1.9921x over previous
#include <cuda_runtime.h>
#include <cuda_bf16.h>
#include <cstdint>

// Problem constants (fixed by metadata): B=32, N=300, C=3, H=W=1024
#define BB 32
#define NN 300
#define HH 1024
#define WW 1024
#define NBOX (BB * NN)          // 9600
#define PLANE (1u << 20)        // 1024*1024
#define NCHUNK 8
#define CHROWS (HH / NCHUNK)    // 128 rows per chunk

// Scratch: per-chunk local column-prefix of (class2 - class1). 128 MiB.
__device__ float g_cc[(size_t)BB * PLANE];
// Per-(batch, chunk, col) chunk totals -> exclusive prefix (offsets). 1 MiB.
__device__ float g_tot[BB * NCHUNK * WW];
// Per-batch bitmask of rows of g_cc that box queries will read.
__device__ unsigned g_rowmask[BB * 32];

__device__ __forceinline__ int clampi(int v, int lo, int hi) {
    return v < lo ? lo : (v > hi ? hi : v);
}

// trunc-toward-zero then clamp — bit-exact vs the reference.
__device__ __forceinline__ void box_coords(const float* __restrict__ boxes, int i,
                                           int& x1, int& x2, int& y1, int& y2) {
    float cx = boxes[i * 4 + 0];
    float cy = boxes[i * 4 + 1];
    float w  = boxes[i * 4 + 2];
    float h  = boxes[i * 4 + 3];
    x1 = clampi((int)((cx - w * 0.5f) * (float)WW), 0, WW - 1);
    x2 = clampi((int)((cx + w * 0.5f) * (float)WW), 0, WW - 1);
    y1 = clampi((int)((cy - h * 0.5f) * (float)HH), 0, HH - 1);
    y2 = clampi((int)((cy + h * 0.5f) * (float)HH), 0, HH - 1);
}

// Kernel 0: zero row masks + output scalar. Tiny.
__global__ void k_zero(float* __restrict__ out) {
    int tid = threadIdx.x;
    for (int i = tid; i < BB * 32; i += blockDim.x) g_rowmask[i] = 0u;
    if (tid == 0) out[0] = 0.0f;
}

// Kernel 1: one thread per box — mark needed rows. 75 blocks x 128.
__global__ void k_mark(const float* __restrict__ boxes,
                       const float* __restrict__ conf) {
    int i = blockIdx.x * blockDim.x + threadIdx.x;
    if (i >= NBOX) return;
    int x1, x2, y1, y2;
    box_coords(boxes, i, x1, x2, y1, y2);
    if ((conf[i] >= 0.3f) && (x2 > x1) && (y2 > y1)) {
        int b = i / NN;
        int rt = y2 - 1;
        atomicOr(&g_rowmask[b * 32 + (rt >> 5)], 1u << (rt & 31));
        if (y1 > 0) {
            int rb = y1 - 1;
            atomicOr(&g_rowmask[b * 32 + (rb >> 5)], 1u << (rb & 31));
        }
    }
}

// Kernel 2: segmented column-prefix of diff = seg[b,2] - seg[b,1].
// grid = (WW/128, NCHUNK, BB), block = 128. Each thread scans 128 rows of one
// column within its chunk: stores LOCAL masked prefix + writes chunk total.
__global__ void k_scan(const float* __restrict__ seg) {
    int b     = blockIdx.z;
    int chunk = blockIdx.y;
    int col   = blockIdx.x * 128 + threadIdx.x;
    int r0    = chunk * CHROWS;

    __shared__ unsigned smask[4];
    if (threadIdx.x < 4)
        smask[threadIdx.x] = g_rowmask[b * 32 + (r0 >> 5) + threadIdx.x];
    __syncthreads();

    const float* __restrict__ p1 = seg + ((size_t)(b * 3 + 1)) * PLANE + (size_t)r0 * WW + col;
    const float* __restrict__ p2 = seg + ((size_t)(b * 3 + 2)) * PLANE + (size_t)r0 * WW + col;
    float* __restrict__ pc = g_cc + ((size_t)b) * PLANE + (size_t)r0 * WW + col;

    float run = 0.0f;
#pragma unroll
    for (int w = 0; w < 4; ++w) {
        unsigned m = smask[w];
#pragma unroll
        for (int g = 0; g < 4; ++g) {
            float d[8];
#pragma unroll
            for (int i = 0; i < 8; ++i)
                d[i] = p2[(size_t)i * WW] - p1[(size_t)i * WW];
#pragma unroll
            for (int i = 0; i < 8; ++i) {
                run += d[i];
                if ((m >> (g * 8 + i)) & 1u) pc[(size_t)i * WW] = run;
            }
            p1 += 8 * WW;
            p2 += 8 * WW;
            pc += 8 * WW;
        }
    }
    g_tot[(b * NCHUNK + chunk) * WW + col] = run;
}

// Kernel 3: turn chunk totals into per-column exclusive prefixes (in place).
// 32768 threads, one per (batch, col).
__global__ void k_offpre() {
    int idx = blockIdx.x * blockDim.x + threadIdx.x;   // 0..BB*WW-1
    int b = idx >> 10;
    int col = idx & (WW - 1);
    float run = 0.0f;
#pragma unroll
    for (int c = 0; c < NCHUNK; ++c) {
        int o = (b * NCHUNK + c) * WW + col;
        float v = g_tot[o];
        g_tot[o] = run;
        run += v;
    }
}

// Kernel 4: one block per box. Reduce row segments (+chunk offsets), relu,
// weight by confidence, atomicAdd into the scalar.
__global__ void k_box(const float* __restrict__ boxes,
                      const float* __restrict__ conf,
                      float* __restrict__ out) {
    int i = blockIdx.x;
    int x1, x2, y1, y2;
    box_coords(boxes, i, x1, x2, y1, y2);
    float cf = conf[i];
    if (!((cf >= 0.3f) && (x2 > x1) && (y2 > y1))) return;

    int b = i / NN;
    int rt = y2 - 1;
    int ct = rt / CHROWS;
    const float* __restrict__ top  = g_cc + ((size_t)b) * PLANE + (size_t)rt * WW;
    const float* __restrict__ offt = g_tot + (b * NCHUNK + ct) * WW;

    float s = 0.0f;
    int tx = (int)threadIdx.x;
    if (y1 > 0) {
        int rb = y1 - 1;
        int cb = rb / CHROWS;
        const float* __restrict__ bot = g_cc + ((size_t)b) * PLANE + (size_t)rb * WW;
        if (ct == cb) {
            for (int x = x1 + tx; x < x2; x += (int)blockDim.x)
                s += top[x] - bot[x];
        } else {
            const float* __restrict__ offb = g_tot + (b * NCHUNK + cb) * WW;
            for (int x = x1 + tx; x < x2; x += (int)blockDim.x)
                s += (top[x] - bot[x]) + (offt[x] - offb[x]);
        }
    } else {
        if (ct == 0) {
            for (int x = x1 + tx; x < x2; x += (int)blockDim.x)
                s += top[x];
        } else {
            for (int x = x1 + tx; x < x2; x += (int)blockDim.x)
                s += top[x] + offt[x];
        }
    }

    __shared__ float red[4];
#pragma unroll
    for (int off = 16; off > 0; off >>= 1)
        s += __shfl_down_sync(0xFFFFFFFFu, s, off);
    if ((threadIdx.x & 31) == 0) red[threadIdx.x >> 5] = s;
    __syncthreads();
    if (threadIdx.x == 0) {
        float tot = red[0] + red[1] + red[2] + red[3];
        float area = (float)((y2 - y1) * (x2 - x1));
        float pb = fmaxf(tot / area, 0.0f) * cf;
        atomicAdd(out, pb * (1.0f / (float)NBOX));
    }
}

extern "C" void kernel_launch(void* const* d_in, const int* in_sizes, int n_in,
                              void* d_out, int out_size) {
    const float* boxes = (const float*)d_in[0];   // (32,300,4)
    const float* conf  = (const float*)d_in[1];   // (32,300)
    const float* seg   = (const float*)d_in[2];   // (32,3,1024,1024)
    float* out = (float*)d_out;

    k_zero<<<1, 1024>>>(out);
    k_mark<<<(NBOX + 127) / 128, 128>>>(boxes, conf);
    dim3 gscan(WW / 128, NCHUNK, BB);
    k_scan<<<gscan, 128>>>(seg);
    k_offpre<<<(BB * WW) / 1024, 1024>>>();
    k_box<<<NBOX, 128>>>(boxes, conf, out);
}